// round 10
// baseline (speedup 1.0000x reference)
#include <cuda_runtime.h>
#include <float.h>

#define BT     (16 * 512)   // 8192 pairs
#define IDIM   80
#define HDIM   512
#define NSHIFT 159
#define PAD    79
#define SKP    248

#define NSLICE 4
#define SLICE_PAIRS (BT / NSLICE)        // 2048

// Scratch for x_attn (allocation-free rule: __device__ global)
__device__ float g_xattn[BT * IDIM];

__device__ __forceinline__ float warpReduceSum(float v) {
#pragma unroll
    for (int o = 16; o; o >>= 1) v += __shfl_xor_sync(0xffffffffu, v, o);
    return v;
}
__device__ __forceinline__ float warpReduceMax(float v) {
#pragma unroll
    for (int o = 16; o; o >>= 1) v = fmaxf(v, __shfl_xor_sync(0xffffffffu, v, o));
    return v;
}

// ---------------------------------------------------------------------------
// Kernel 1 (R6/R8-validated numerics; + pair0 slice offset)
// ---------------------------------------------------------------------------
#define PAIRS_PER_BLK 8
__global__ __launch_bounds__(256) void attn_kernel(
    const float* __restrict__ x, const float* __restrict__ y,
    float* __restrict__ xattn, int pair0)
{
    const int warp = threadIdx.x >> 5;
    const int lane = threadIdx.x & 31;
    const int p    = pair0 + blockIdx.x * PAIRS_PER_BLK + warp;

    __shared__ float kp[PAIRS_PER_BLK][SKP];
    __shared__ float ys[PAIRS_PER_BLK][IDIM];
    float* kpw = kp[warp];
    float* ysw = ys[warp];

    for (int i = lane; i < SKP; i += 32) kpw[i] = 0.0f;
    __syncwarp();

    const float* xp = x + (size_t)p * IDIM;
    const float* yp = y + (size_t)p * IDIM;
    float yn2 = 0.0f;
    for (int i = lane; i < IDIM; i += 32) {
        kpw[PAD + i] = xp[i];
        float v = yp[i];
        ysw[i] = v;
        yn2 = fmaf(v, v, yn2);
    }
    yn2 = warpReduceSum(yn2);
    __syncwarp();

    const int base = lane * 5;
    float w0 = kpw[base + 0], w1 = kpw[base + 1], w2 = kpw[base + 2],
          w3 = kpw[base + 3], w4 = kpw[base + 4];
    const float i0 = w0, i1 = w1, i2 = w2, i3 = w3;

    float d0 = 0, d1 = 0, d2 = 0, d3 = 0, d4 = 0, core = 0;
#pragma unroll
    for (int i = 0; i < IDIM; ++i) {
        float yv = ysw[i];
        d0 = fmaf(w0, yv, d0);
        d1 = fmaf(w1, yv, d1);
        d2 = fmaf(w2, yv, d2);
        d3 = fmaf(w3, yv, d3);
        d4 = fmaf(w4, yv, d4);
        if (i < IDIM - 4) core = fmaf(w4, w4, core);
        w0 = w1; w1 = w2; w2 = w3; w3 = w4;
        w4 = kpw[base + 5 + i];
    }

    const float t0 = kpw[base + 80], t1 = kpw[base + 81],
                t2 = kpw[base + 82], t3 = kpw[base + 83];
    const float H3 = i3 * i3;
    const float H2 = fmaf(i2, i2, H3);
    const float H1 = fmaf(i1, i1, H2);
    const float H0 = fmaf(i0, i0, H1);
    const float T1 = t0 * t0;
    const float T2 = fmaf(t1, t1, T1);
    const float T3 = fmaf(t2, t2, T2);
    const float T4 = fmaf(t3, t3, T3);

    float dotv[5] = {d0, d1, d2, d3, d4};
    float n2v[5];
    n2v[0] = H0 + core;
    n2v[1] = (H1 + core) + T1;
    n2v[2] = (H2 + core) + T2;
    n2v[3] = (H3 + core) + T3;
    n2v[4] = core + T4;

    const float yn = sqrtf(yn2);
    float best = -FLT_MAX;
    int   bidx = 0;
#pragma unroll
    for (int j = 0; j < 5; ++j) {
        int s = base + j;
        if (s < NSHIFT) {
            float den = sqrtf(n2v[j]) * yn;
            float sim = (den > 0.0f) ? (dotv[j] / den) : 0.0f;
            if (sim > best) { best = sim; bidx = s; }
        }
    }
#pragma unroll
    for (int o = 16; o; o >>= 1) {
        float ov = __shfl_xor_sync(0xffffffffu, best, o);
        int   oi = __shfl_xor_sync(0xffffffffu, bidx, o);
        if (ov > best || (ov == best && oi < bidx)) { best = ov; bidx = oi; }
    }
    const int bs = bidx;

    float xa[3], sc[3];
    float m = -FLT_MAX;
#pragma unroll
    for (int t = 0; t < 3; ++t) {
        int i = lane + t * 32;
        if (i < IDIM) {
            xa[t] = kpw[bs + i];
            sc[t] = xa[t] * ysw[i];
            m = fmaxf(m, sc[t]);
        }
    }
    m = warpReduceMax(m);
    float sum = 0.0f, e[3];
#pragma unroll
    for (int t = 0; t < 3; ++t) {
        int i = lane + t * 32;
        if (i < IDIM) { e[t] = expf((sc[t] - m) * 0.1f); sum += e[t]; }
    }
    sum = warpReduceSum(sum);
    const float inv = 1.0f / sum;
#pragma unroll
    for (int t = 0; t < 3; ++t) {
        int i = lane + t * 32;
        if (i < IDIM) xattn[(size_t)p * IDIM + i] = xa[t] * (e[t] * inv);
    }
}

// ---------------------------------------------------------------------------
// Kernel 2 (R8-validated tf32 single-pass mma; + bm0 slice offset)
// ---------------------------------------------------------------------------
#define SSTR 84

__device__ __forceinline__ unsigned f2tf(float f) {
    unsigned r;
    asm("cvt.rna.tf32.f32 %0, %1;" : "=r"(r) : "f"(f));
    return r;
}

__device__ __forceinline__ void mma_tf32(float d[4], const unsigned a[4],
                                         const unsigned b[2]) {
    asm("mma.sync.aligned.m16n8k8.row.col.f32.tf32.tf32.f32 "
        "{%0,%1,%2,%3}, {%4,%5,%6,%7}, {%8,%9}, {%0,%1,%2,%3};"
        : "+f"(d[0]), "+f"(d[1]), "+f"(d[2]), "+f"(d[3])
        : "r"(a[0]), "r"(a[1]), "r"(a[2]), "r"(a[3]), "r"(b[0]), "r"(b[1]));
}

__global__ __launch_bounds__(256, 2) void gemm_kernel(
    const float* __restrict__ A, const float* __restrict__ W,
    const float* __restrict__ bias, float* __restrict__ out, int bm0)
{
    extern __shared__ unsigned smem_u[];
    unsigned* As = smem_u;
    unsigned* Bs = smem_u + 128 * SSTR;

    const int bn  = blockIdx.x * 128;
    const int bm  = bm0 + blockIdx.y * 128;
    const int tid = threadIdx.x;
    const int warp = tid >> 5, lane = tid & 31;
    const int wm = warp >> 2;
    const int wn = warp & 3;
    const int g  = lane >> 2;
    const int t  = lane & 3;

#pragma unroll
    for (int it = 0; it < 10; ++it) {
        int idx = tid + it * 256;
        int row = idx / 20;
        int k4  = (idx % 20) * 4;
        float4 a = *reinterpret_cast<const float4*>(A + (size_t)(bm + row) * IDIM + k4);
        uint4 ta = make_uint4(f2tf(a.x), f2tf(a.y), f2tf(a.z), f2tf(a.w));
        *reinterpret_cast<uint4*>(&As[row * SSTR + k4]) = ta;
        float4 b = *reinterpret_cast<const float4*>(W + (size_t)(bn + row) * IDIM + k4);
        uint4 tb = make_uint4(f2tf(b.x), f2tf(b.y), f2tf(b.z), f2tf(b.w));
        *reinterpret_cast<uint4*>(&Bs[row * SSTR + k4]) = tb;
    }
    __syncthreads();

    float d[4][4][4];
#pragma unroll
    for (int mt = 0; mt < 4; ++mt)
#pragma unroll
        for (int nt = 0; nt < 4; ++nt)
#pragma unroll
            for (int r = 0; r < 4; ++r) d[mt][nt][r] = 0.0f;

#pragma unroll
    for (int k0 = 0; k0 < IDIM; k0 += 8) {
        unsigned bf[4][2];
#pragma unroll
        for (int nt = 0; nt < 4; ++nt) {
            int nr = (wn * 32 + nt * 8 + g) * SSTR + k0 + t;
            bf[nt][0] = Bs[nr];
            bf[nt][1] = Bs[nr + 4];
        }
#pragma unroll
        for (int mt = 0; mt < 4; ++mt) {
            int r0 = (wm * 64 + mt * 16 + g) * SSTR + k0 + t;
            unsigned af[4];
            af[0] = As[r0];
            af[1] = As[r0 + 8 * SSTR];
            af[2] = As[r0 + 4];
            af[3] = As[r0 + 8 * SSTR + 4];
#pragma unroll
            for (int nt = 0; nt < 4; ++nt)
                mma_tf32(d[mt][nt], af, bf[nt]);
        }
    }

#pragma unroll
    for (int mt = 0; mt < 4; ++mt) {
#pragma unroll
        for (int nt = 0; nt < 4; ++nt) {
            int row = bm + wm * 64 + mt * 16 + g;
            int col = bn + wn * 32 + nt * 8 + 2 * t;
            float b0 = __ldg(bias + col), b1 = __ldg(bias + col + 1);
            float2 o0 = make_float2(d[mt][nt][0] + b0, d[mt][nt][1] + b1);
            float2 o1 = make_float2(d[mt][nt][2] + b0, d[mt][nt][3] + b1);
            *reinterpret_cast<float2*>(out + (size_t)row * HDIM + col) = o0;
            *reinterpret_cast<float2*>(out + (size_t)(row + 8) * HDIM + col) = o1;
        }
    }
}

extern "C" void kernel_launch(void* const* d_in, const int* in_sizes, int n_in,
                              void* d_out, int out_size)
{
    const float* x    = (const float*)d_in[0];
    const float* y    = (const float*)d_in[1];
    const float* fc1w = (const float*)d_in[2];
    const float* fc1b = (const float*)d_in[3];
    float* out = (float*)d_out;

    float* xattn = nullptr;
    cudaGetSymbolAddress((void**)&xattn, g_xattn);

    const int smem_bytes = 2 * 128 * SSTR * (int)sizeof(unsigned);  // 86016
    cudaFuncSetAttribute(gemm_kernel,
                         cudaFuncAttributeMaxDynamicSharedMemorySize, smem_bytes);

    // ---- try to fork a side stream for attn/gemm pipelining ----
    cudaStream_t s1 = 0;
    cudaEvent_t evA[NSLICE], evJ;
    bool ok = true;
    {
        cudaStreamCaptureMode mode = cudaStreamCaptureModeRelaxed;
        cudaThreadExchangeStreamCaptureMode(&mode);   // relax for create calls
        ok = (cudaStreamCreateWithFlags(&s1, cudaStreamNonBlocking) == cudaSuccess);
        for (int i = 0; i < NSLICE && ok; ++i)
            ok = (cudaEventCreateWithFlags(&evA[i], cudaEventDisableTiming) == cudaSuccess);
        if (ok)
            ok = (cudaEventCreateWithFlags(&evJ, cudaEventDisableTiming) == cudaSuccess);
        cudaThreadExchangeStreamCaptureMode(&mode);   // restore
    }

    if (ok) {
        for (int i = 0; i < NSLICE; ++i) {
            const int p0 = i * SLICE_PAIRS;
            attn_kernel<<<SLICE_PAIRS / PAIRS_PER_BLK, 256>>>(x, y, xattn, p0);
            ok = ok && (cudaEventRecord(evA[i], 0) == cudaSuccess);
            ok = ok && (cudaStreamWaitEvent(s1, evA[i], 0) == cudaSuccess);
            gemm_kernel<<<dim3(HDIM / 128, SLICE_PAIRS / 128), 256, smem_bytes, s1>>>(
                xattn, fc1w, fc1b, out, p0);
        }
        // join side stream back into stream 0
        ok = ok && (cudaEventRecord(evJ, s1) == cudaSuccess);
        ok = ok && (cudaStreamWaitEvent(0, evJ, 0) == cudaSuccess);
        if (ok) return;
    }

    // ---- serial fallback (identical math) ----
    for (int i = 0; i < NSLICE; ++i) {
        const int p0 = i * SLICE_PAIRS;
        attn_kernel<<<SLICE_PAIRS / PAIRS_PER_BLK, 256>>>(x, y, xattn, p0);
    }
    for (int i = 0; i < NSLICE; ++i) {
        const int p0 = i * SLICE_PAIRS;
        gemm_kernel<<<dim3(HDIM / 128, SLICE_PAIRS / 128), 256, smem_bytes>>>(
            xattn, fc1w, fc1b, out, p0);
    }
}

// round 11
// speedup vs baseline: 1.5008x; 1.5008x over previous
#include <cuda_runtime.h>
#include <float.h>

#define BT     (16 * 512)   // 8192 pairs
#define IDIM   80
#define HDIM   512
#define NSHIFT 159
#define PAD    79
#define SKP    248

// Scratch for x_attn (allocation-free rule: __device__ global)
__device__ float g_xattn[BT * IDIM];

__device__ __forceinline__ float warpReduceSum(float v) {
#pragma unroll
    for (int o = 16; o; o >>= 1) v += __shfl_xor_sync(0xffffffffu, v, o);
    return v;
}
__device__ __forceinline__ float warpReduceMax(float v) {
#pragma unroll
    for (int o = 16; o; o >>= 1) v = fmaxf(v, __shfl_xor_sync(0xffffffffu, v, o));
    return v;
}

// ---------------------------------------------------------------------------
// Kernel 1 (UNCHANGED from R8 — validated): warp-per-pair sliding window,
// shared-core all-positive norm decomposition.
// ---------------------------------------------------------------------------
#define PAIRS_PER_BLK 8
__global__ __launch_bounds__(256) void attn_kernel(
    const float* __restrict__ x, const float* __restrict__ y,
    float* __restrict__ xattn)
{
    const int warp = threadIdx.x >> 5;
    const int lane = threadIdx.x & 31;
    const int p    = blockIdx.x * PAIRS_PER_BLK + warp;

    __shared__ float kp[PAIRS_PER_BLK][SKP];
    __shared__ float ys[PAIRS_PER_BLK][IDIM];
    float* kpw = kp[warp];
    float* ysw = ys[warp];

    for (int i = lane; i < SKP; i += 32) kpw[i] = 0.0f;
    __syncwarp();

    const float* xp = x + (size_t)p * IDIM;
    const float* yp = y + (size_t)p * IDIM;
    float yn2 = 0.0f;
    for (int i = lane; i < IDIM; i += 32) {
        kpw[PAD + i] = xp[i];
        float v = yp[i];
        ysw[i] = v;
        yn2 = fmaf(v, v, yn2);
    }
    yn2 = warpReduceSum(yn2);
    __syncwarp();

    const int base = lane * 5;
    float w0 = kpw[base + 0], w1 = kpw[base + 1], w2 = kpw[base + 2],
          w3 = kpw[base + 3], w4 = kpw[base + 4];
    const float i0 = w0, i1 = w1, i2 = w2, i3 = w3;

    float d0 = 0, d1 = 0, d2 = 0, d3 = 0, d4 = 0, core = 0;
#pragma unroll
    for (int i = 0; i < IDIM; ++i) {
        float yv = ysw[i];
        d0 = fmaf(w0, yv, d0);
        d1 = fmaf(w1, yv, d1);
        d2 = fmaf(w2, yv, d2);
        d3 = fmaf(w3, yv, d3);
        d4 = fmaf(w4, yv, d4);
        if (i < IDIM - 4) core = fmaf(w4, w4, core);
        w0 = w1; w1 = w2; w2 = w3; w3 = w4;
        w4 = kpw[base + 5 + i];
    }

    const float t0 = kpw[base + 80], t1 = kpw[base + 81],
                t2 = kpw[base + 82], t3 = kpw[base + 83];
    const float H3 = i3 * i3;
    const float H2 = fmaf(i2, i2, H3);
    const float H1 = fmaf(i1, i1, H2);
    const float H0 = fmaf(i0, i0, H1);
    const float T1 = t0 * t0;
    const float T2 = fmaf(t1, t1, T1);
    const float T3 = fmaf(t2, t2, T2);
    const float T4 = fmaf(t3, t3, T3);

    float dotv[5] = {d0, d1, d2, d3, d4};
    float n2v[5];
    n2v[0] = H0 + core;
    n2v[1] = (H1 + core) + T1;
    n2v[2] = (H2 + core) + T2;
    n2v[3] = (H3 + core) + T3;
    n2v[4] = core + T4;

    const float yn = sqrtf(yn2);
    float best = -FLT_MAX;
    int   bidx = 0;
#pragma unroll
    for (int j = 0; j < 5; ++j) {
        int s = base + j;
        if (s < NSHIFT) {
            float den = sqrtf(n2v[j]) * yn;
            float sim = (den > 0.0f) ? (dotv[j] / den) : 0.0f;
            if (sim > best) { best = sim; bidx = s; }
        }
    }
#pragma unroll
    for (int o = 16; o; o >>= 1) {
        float ov = __shfl_xor_sync(0xffffffffu, best, o);
        int   oi = __shfl_xor_sync(0xffffffffu, bidx, o);
        if (ov > best || (ov == best && oi < bidx)) { best = ov; bidx = oi; }
    }
    const int bs = bidx;

    float xa[3], sc[3];
    float m = -FLT_MAX;
#pragma unroll
    for (int t = 0; t < 3; ++t) {
        int i = lane + t * 32;
        if (i < IDIM) {
            xa[t] = kpw[bs + i];
            sc[t] = xa[t] * ysw[i];
            m = fmaxf(m, sc[t]);
        }
    }
    m = warpReduceMax(m);
    float sum = 0.0f, e[3];
#pragma unroll
    for (int t = 0; t < 3; ++t) {
        int i = lane + t * 32;
        if (i < IDIM) { e[t] = expf((sc[t] - m) * 0.1f); sum += e[t]; }
    }
    sum = warpReduceSum(sum);
    const float inv = 1.0f / sum;
#pragma unroll
    for (int t = 0; t < 3; ++t) {
        int i = lane + t * 32;
        if (i < IDIM) xattn[(size_t)p * IDIM + i] = xa[t] * (e[t] * inv);
    }
}

// ---------------------------------------------------------------------------
// Kernel 2: out[8192,512] = xattn[8192,80] @ W[512,80]^T + bias
// Single-pass fp16 mma.m16n8k16 with fp32 accumulate (same 10-bit mantissa
// as tf32, half the mma instructions). Fragment indexing = R4-validated
// bf16-k16 mapping; fp16 conversion once at tile fill.
// Block 128x128, 8 warps (2x4), warp tile 64x32 (4x4 mma tiles).
// ---------------------------------------------------------------------------
#define SP2 44   // uint (4B) stride per row: (44g + t) mod 32 all-distinct

__device__ __forceinline__ unsigned f16pack(float v0, float v1) {
    unsigned r;
    asm("cvt.rn.f16x2.f32 %0, %1, %2;" : "=r"(r) : "f"(v1), "f"(v0));
    return r;
}

__device__ __forceinline__ void mma_f16(float d[4],
                                        unsigned a0, unsigned a1,
                                        unsigned a2, unsigned a3,
                                        unsigned b0, unsigned b1) {
    asm("mma.sync.aligned.m16n8k16.row.col.f32.f16.f16.f32 "
        "{%0,%1,%2,%3}, {%4,%5,%6,%7}, {%8,%9}, {%0,%1,%2,%3};"
        : "+f"(d[0]), "+f"(d[1]), "+f"(d[2]), "+f"(d[3])
        : "r"(a0), "r"(a1), "r"(a2), "r"(a3), "r"(b0), "r"(b1));
}

__global__ __launch_bounds__(256, 2) void gemm_kernel(
    const float* __restrict__ A, const float* __restrict__ W,
    const float* __restrict__ bias, float* __restrict__ out)
{
    extern __shared__ unsigned smem_u[];
    unsigned* As = smem_u;              // [128][SP2] fp16x2 pairs (k-pair major)
    unsigned* Bs = smem_u + 128 * SP2;  // [128][SP2]

    const int bn  = blockIdx.x * 128;
    const int bm  = blockIdx.y * 128;
    const int tid = threadIdx.x;
    const int warp = tid >> 5, lane = tid & 31;
    const int wm = warp >> 2;       // 0..1  (64 rows each)
    const int wn = warp & 3;        // 0..3  (32 cols each)
    const int g  = lane >> 2;
    const int t  = lane & 3;

    // Fill: 128 rows x 20 float4 each -> 2 fp16x2 pairs per float4
#pragma unroll
    for (int it = 0; it < 10; ++it) {
        int idx = tid + it * 256;
        int row = idx / 20;
        int k4  = (idx % 20) * 4;
        int c   = k4 >> 1;          // pair index (even)

        float4 a = *reinterpret_cast<const float4*>(A + (size_t)(bm + row) * IDIM + k4);
        *reinterpret_cast<uint2*>(&As[row * SP2 + c]) =
            make_uint2(f16pack(a.x, a.y), f16pack(a.z, a.w));

        float4 b = *reinterpret_cast<const float4*>(W + (size_t)(bn + row) * IDIM + k4);
        *reinterpret_cast<uint2*>(&Bs[row * SP2 + c]) =
            make_uint2(f16pack(b.x, b.y), f16pack(b.z, b.w));
    }
    __syncthreads();

    float d[4][4][4];
#pragma unroll
    for (int mt = 0; mt < 4; ++mt)
#pragma unroll
        for (int nt = 0; nt < 4; ++nt)
#pragma unroll
            for (int r = 0; r < 4; ++r) d[mt][nt][r] = 0.0f;

    // K = 80 -> 5 chunks of k16 (8 pairs each)
#pragma unroll
    for (int kc = 0; kc < 5; ++kc) {
        const int kb = kc * 8 + t;

        unsigned b0[4], b1[4];
#pragma unroll
        for (int nt = 0; nt < 4; ++nt) {
            int nr = (wn * 32 + nt * 8 + g) * SP2 + kb;
            b0[nt] = Bs[nr];
            b1[nt] = Bs[nr + 4];
        }

#pragma unroll
        for (int mt = 0; mt < 4; ++mt) {
            int r0 = (wm * 64 + mt * 16 + g) * SP2 + kb;
            unsigned a0 = As[r0];
            unsigned a1 = As[r0 + 8 * SP2];
            unsigned a2 = As[r0 + 4];
            unsigned a3 = As[r0 + 8 * SP2 + 4];
#pragma unroll
            for (int nt = 0; nt < 4; ++nt)
                mma_f16(d[mt][nt], a0, a1, a2, a3, b0[nt], b1[nt]);
        }
    }

    // Epilogue: c0,c1 -> (row, 2t..2t+1); c2,c3 -> (row+8, 2t..2t+1)
#pragma unroll
    for (int mt = 0; mt < 4; ++mt) {
#pragma unroll
        for (int nt = 0; nt < 4; ++nt) {
            int row = bm + wm * 64 + mt * 16 + g;
            int col = bn + wn * 32 + nt * 8 + 2 * t;
            float b0 = __ldg(bias + col), b1 = __ldg(bias + col + 1);
            float2 o0 = make_float2(d[mt][nt][0] + b0, d[mt][nt][1] + b1);
            float2 o1 = make_float2(d[mt][nt][2] + b0, d[mt][nt][3] + b1);
            *reinterpret_cast<float2*>(out + (size_t)row * HDIM + col) = o0;
            *reinterpret_cast<float2*>(out + (size_t)(row + 8) * HDIM + col) = o1;
        }
    }
}

extern "C" void kernel_launch(void* const* d_in, const int* in_sizes, int n_in,
                              void* d_out, int out_size)
{
    const float* x    = (const float*)d_in[0];
    const float* y    = (const float*)d_in[1];
    const float* fc1w = (const float*)d_in[2];
    const float* fc1b = (const float*)d_in[3];
    float* out = (float*)d_out;

    float* xattn = nullptr;
    cudaGetSymbolAddress((void**)&xattn, g_xattn);

    attn_kernel<<<BT / PAIRS_PER_BLK, 256>>>(x, y, xattn);

    const int smem_bytes = 2 * 128 * SP2 * (int)sizeof(unsigned);  // 45056
    cudaFuncSetAttribute(gemm_kernel,
                         cudaFuncAttributeMaxDynamicSharedMemorySize, smem_bytes);
    gemm_kernel<<<dim3(HDIM / 128, BT / 128), 256, smem_bytes>>>(xattn, fc1w, fc1b, out);
}